// round 13
// baseline (speedup 1.0000x reference)
#include <cuda_runtime.h>

// Problem constants (fixed shapes per reference: B=128, C=1, H=W=512, BINS=256)
#define NBINS      256
#define HEIGHT_RT  0.05f
#define NB         128                 // batch
#define NPER       262144              // 512*512 elems per sample
#define CHUNKS     32                  // hist units per sample
#define CHUNK_EL   (NPER / CHUNKS)     // 8192 elems per unit
#define NUNITS     (NB * CHUNKS)       // 4096 hist units
#define OUT_X      ((size_t)NB * NPER) // big output, then NB values
#define NBLOCKS    740                 // 5 per SM on 148 SMs -> all co-resident
#define NTHREADS   256
#define TILES      8192                // scale tiles of 1024 float4

// Scratch (no allocations). Every used slot fully overwritten each call.
__device__ unsigned int g_hist_partial[NUNITS * NBINS];   // 4 MB
__device__ float        g_w[NB];
__device__ unsigned int g_bar_cnt = 0;     // arrival counter (returns to 0)
__device__ unsigned int g_bar_gen = 0;     // generation (monotonic across replays)

// Grid-wide barrier: safe because all NBLOCKS are co-resident (launch_bounds
// guarantees 5 CTAs/SM residency; 740 = 5*148).
__device__ __forceinline__ void grid_barrier() {
    __syncthreads();
    if (threadIdx.x == 0) {
        __threadfence();                                   // publish my writes
        unsigned int g = *((volatile unsigned int*)&g_bar_gen);
        unsigned int t = atomicAdd(&g_bar_cnt, 1u);
        if (t == NBLOCKS - 1) {
            g_bar_cnt = 0;
            __threadfence();
            atomicAdd(&g_bar_gen, 1u);                     // release
        } else {
            while (*((volatile unsigned int*)&g_bar_gen) == g) __nanosleep(64);
        }
        __threadfence();                                   // acquire
    }
    __syncthreads();
}

// ---------------------------------------------------------------------------
// Single persistent kernel: hist -> (barrier) -> mlp -> (barrier) -> scale.
// R6 measured this structure at ~267 MB total DRAM traffic (reverse phase-3
// sweep hits L2 for most of the x re-read); this version runs it at 5 CTAs/SM
// instead of 2 (40 warps/SM) to remove the latency-bound behavior.
// ---------------------------------------------------------------------------
__global__ __launch_bounds__(NTHREADS, 5) void fused_kernel(
    const float* __restrict__ x,
    const float* __restrict__ W1, const float* __restrict__ b1,
    const float* __restrict__ W2, const float* __restrict__ b2,
    const float* __restrict__ W3, const float* __restrict__ b3,
    const float* __restrict__ W4, const float* __restrict__ b4,
    float* __restrict__ out, float* __restrict__ out_value)
{
    __shared__ unsigned int sh[8][NBINS];     // 8 KB: warp-private hist copies
    const int tid  = threadIdx.x;             // 0..255
    const int lane = tid & 31;
    const int warp = tid >> 5;                // 0..7
    const int bid  = blockIdx.x;

    // ============================ Phase 1: histogram =======================
    // 4096 units over 740 blocks: 5-6 units each (<=18% tail imbalance).
    for (int unit = bid; unit < NUNITS; unit += NBLOCKS) {
        const int sample = unit >> 5;
        const int chunk  = unit & 31;

        #pragma unroll
        for (int c = 0; c < 8; c++) sh[c][tid] = 0u;
        __syncthreads();

        const float4* __restrict__ p =
            (const float4*)(x + (size_t)sample * NPER + (size_t)chunk * CHUNK_EL);
        // 2048 float4 per unit; 8 per thread
        #pragma unroll
        for (int j = 0; j < 8; j++) {
            float4 v = p[j * 256 + tid];
            float vals[4] = {v.x, v.y, v.z, v.w};
            #pragma unroll
            for (int k = 0; k < 4; k++) {
                float f = vals[k];
                if (f >= 0.0f && f <= 1.0f) {     // torch.histc: out-of-range ignored
                    int b = (int)(f * 256.0f);    // floor (f >= 0)
                    if (b > 255) b = 255;         // f == 1.0 -> last bin
                    atomicAdd(&sh[warp][b], 1u);
                }
            }
        }
        __syncthreads();

        unsigned int s = 0;
        #pragma unroll
        for (int c = 0; c < 8; c++) s += sh[c][tid];
        g_hist_partial[(size_t)unit * NBINS + tid] = s;
        __syncthreads();
    }

    grid_barrier();

    // ============================ Phase 2: value + MLP =====================
    // Blocks 0..NB-1 each handle one sample; others fall through to barrier.
    if (bid < NB) {
        float*        s_h   = (float*)&sh[0][0];          // reuse smem: 256 floats
        unsigned int* s_red = &sh[4][0];                  // 8 slots
        float*        s_l1p = (float*)&sh[5][0];          // 8*32 floats
        float*        s_h1  = (float*)&sh[6][0];          // 32
        float*        s_h2  = (float*)&sh[6][32];         // 64
        float*        s_h3  = (float*)&sh[6][96];         // 128
        float*        s_p   = (float*)&sh[6][224];        // 4
        unsigned int* s_key = &sh[4][16];

        // Sum 32 chunk partials -> histogram (bin = tid, 256 threads)
        unsigned int cnt;
        {
            unsigned int s = 0;
            const unsigned int* p = &g_hist_partial[(size_t)bid * CHUNKS * NBINS + tid];
            #pragma unroll
            for (int c = 0; c < CHUNKS; c++) s += p[c * NBINS];
            cnt = s;
            s_h[tid] = (float)s;
        }

        // First-occurrence argmax, packed key (count<<8)|(255-bin).
        // counts <= 262144 < 2^19 -> fits 27 bits; ties go to LOWEST index.
        unsigned int key = (cnt << 8) | (unsigned)(255 - tid);
        #pragma unroll
        for (int o = 16; o > 0; o >>= 1) {
            unsigned int other = __shfl_down_sync(0xffffffffu, key, o);
            if (other > key) key = other;
        }
        if (lane == 0) s_red[warp] = key;
        __syncthreads();
        if (tid == 0) {
            unsigned int k = s_red[0];
            #pragma unroll
            for (int i = 1; i < 8; i++) if (s_red[i] > k) k = s_red[i];
            *s_key = k;
        }
        __syncthreads();

        const int   am = 255 - (int)(*s_key & 255u);
        const float ch = (float)(*s_key >> 8) * HEIGHT_RT;
        __syncthreads();   // protect s_red reuse below

        // First i >= am with h[i] <= ch; default 0 if none.
        int mini = (tid >= am && !(s_h[tid] > ch)) ? tid : 0x7fffffff;
        #pragma unroll
        for (int o = 16; o > 0; o >>= 1) {
            int other = __shfl_down_sync(0xffffffffu, mini, o);
            if (other < mini) mini = other;
        }
        if (lane == 0) s_red[warp] = (unsigned)mini;
        __syncthreads();
        if (tid == 0) {
            int m = (int)s_red[0];
            #pragma unroll
            for (int i = 1; i < 8; i++) if ((int)s_red[i] < m) m = (int)s_red[i];
            if (m == 0x7fffffff) m = 0;
            out_value[bid] = (float)m / (float)NBINS;
        }

        // Layer 1: 256 -> 32  (8 partials x 32 outputs)
        {
            const int o = tid & 31, pp = tid >> 5;
            float acc = (pp == 0) ? b1[o] : 0.0f;
            const float* w = W1 + o * 256 + pp * 32;
            const float* h = s_h + pp * 32;
            #pragma unroll
            for (int k = 0; k < 32; k++) acc = fmaf(h[k], w[k], acc);
            s_l1p[pp * 32 + o] = acc;
        }
        __syncthreads();
        if (tid < 32) {
            float a = 0.0f;
            #pragma unroll
            for (int pp = 0; pp < 8; pp++) a += s_l1p[pp * 32 + tid];
            s_h1[tid] = fmaxf(a, 0.0f);
        }
        __syncthreads();

        // Layer 2: 32 -> 64
        if (tid < 64) {
            float acc = b2[tid];
            const float* w = W2 + tid * 32;
            #pragma unroll
            for (int k = 0; k < 32; k++) acc = fmaf(s_h1[k], w[k], acc);
            s_h2[tid] = fmaxf(acc, 0.0f);
        }
        __syncthreads();

        // Layer 3: 64 -> 128
        if (tid < 128) {
            float acc = b3[tid];
            const float* w = W3 + tid * 64;
            #pragma unroll
            for (int k = 0; k < 64; k++) acc = fmaf(s_h2[k], w[k], acc);
            s_h3[tid] = fmaxf(acc, 0.0f);
        }
        __syncthreads();

        // Layer 4: 128 -> 1 (first 4 warps)
        float part = (tid < 128) ? s_h3[tid] * W4[tid] : 0.0f;
        #pragma unroll
        for (int o = 16; o > 0; o >>= 1)
            part += __shfl_down_sync(0xffffffffu, part, o);
        if (lane == 0 && warp < 4) s_p[warp] = part;
        __syncthreads();
        if (tid == 0)
            g_w[bid] = s_p[0] + s_p[1] + s_p[2] + s_p[3] + b4[0];
    }

    grid_barrier();

    // ============================ Phase 3: scale ===========================
    // Reverse traversal: phase 1 read x front-to-back, so the tail of x is
    // L2-resident; reading tail-first converts most re-reads into L2 hits
    // (R6 measured ~267 MB total vs 402 MB naive). __ldcs = evict-first on
    // this last use; __stcs streams the out writes.
    for (int t = bid; t < TILES; t += NBLOCKS) {
        const int tile   = TILES - 1 - t;
        const int sample = tile >> 6;               // 64 tiles per sample
        const float w    = g_w[sample];

        const size_t base = (size_t)tile * 1024 + tid;
        const float4* __restrict__ xin = (const float4*)x   + base;
        float4* __restrict__       o   = (float4*)out       + base;
        #pragma unroll
        for (int j = 0; j < 4; j++) {
            float4 v = __ldcs(xin + j * 256);
            v.x *= w; v.y *= w; v.z *= w; v.w *= w;
            __stcs(o + j * 256, v);
        }
    }
}

// ---------------------------------------------------------------------------
extern "C" void kernel_launch(void* const* d_in, const int* in_sizes, int n_in,
                              void* d_out, int out_size)
{
    const float* x  = (const float*)d_in[0];
    const float* W1 = (const float*)d_in[1];
    const float* b1 = (const float*)d_in[2];
    const float* W2 = (const float*)d_in[3];
    const float* b2 = (const float*)d_in[4];
    const float* W3 = (const float*)d_in[5];
    const float* b3 = (const float*)d_in[6];
    const float* W4 = (const float*)d_in[7];
    const float* b4 = (const float*)d_in[8];

    float* out       = (float*)d_out;
    float* out_value = out + OUT_X;

    fused_kernel<<<NBLOCKS, NTHREADS>>>(x, W1, b1, W2, b2, W3, b3, W4, b4,
                                        out, out_value);
    (void)in_sizes; (void)n_in; (void)out_size;
}

// round 14
// speedup vs baseline: 1.1772x; 1.1772x over previous
#include <cuda_runtime.h>

// Problem constants (fixed shapes per reference: B=128, C=1, H=W=512, BINS=256)
#define NBINS      256
#define HEIGHT_RT  0.05f
#define NB         128                 // batch
#define NPER       262144              // 512*512 elems per sample
#define CHUNKS     8                   // hist blocks per sample
#define CHUNK_EL   (NPER / CHUNKS)     // 32768 elems per hist block
#define OUT_X      ((size_t)NB * NPER) // big output, then NB values
#define TILES      8192                // scale tiles of 1024 float4

// Scratch (no allocations). Every slot fully overwritten each call.
__device__ unsigned int g_hist_partial[NB * CHUNKS * NBINS];   // 1 MB
__device__ float        g_w[NB];
__device__ volatile unsigned int g_ready[NB];   // reset by hist launch

// ---------------------------------------------------------------------------
// Kernel 1: per-(sample,chunk) histogram. grid = (CHUNKS, NB), 256 threads.
// Warp-private smem copies + atomics (measured ~26 us, DRAM 66%, at the
// ATOMS structural floor). chunk==0 blocks also reset the ready flags
// (launch boundary orders this before the scale+mlp kernel).
// ---------------------------------------------------------------------------
__global__ __launch_bounds__(256) void hist_kernel(const float* __restrict__ x) {
    __shared__ unsigned int sh[8][NBINS];
    const int tid    = threadIdx.x;          // 0..255
    const int warp   = tid >> 5;
    const int sample = blockIdx.y;
    const int chunk  = blockIdx.x;

    if (chunk == 0 && tid == 0) g_ready[sample] = 0u;

    #pragma unroll
    for (int c = 0; c < 8; c++) sh[c][tid] = 0u;
    __syncthreads();

    const float4* __restrict__ p =
        (const float4*)(x + (size_t)sample * NPER + (size_t)chunk * CHUNK_EL);
    // 8192 float4 per block; 32 per thread
    #pragma unroll 8
    for (int j = 0; j < 32; j++) {
        float4 v = p[j * 256 + tid];
        float vals[4] = {v.x, v.y, v.z, v.w};
        #pragma unroll
        for (int k = 0; k < 4; k++) {
            float f = vals[k];
            if (f >= 0.0f && f <= 1.0f) {        // torch.histc: out-of-range ignored
                int b = (int)(f * 256.0f);       // floor (f >= 0)
                if (b > 255) b = 255;            // f == 1.0 -> last bin
                atomicAdd(&sh[warp][b], 1u);
            }
        }
    }
    __syncthreads();

    unsigned int s = 0;
    #pragma unroll
    for (int c = 0; c < 8; c++) s += sh[c][tid];
    g_hist_partial[((size_t)sample * CHUNKS + chunk) * NBINS + tid] = s;
}

// ---------------------------------------------------------------------------
// Kernel 2 (fused): bids 0..NB-1 = value+MLP (wave-1 resident, publish g_w
// then set flag); bids NB.. = R7's EXACT scale pass (reverse sweep, 1024
// float4 tiles, __ldcs/__stcs), spin-waiting on the sample's flag first.
// Flag values identical every replay -> deterministic.
// ---------------------------------------------------------------------------
__global__ __launch_bounds__(256) void scale_mlp_kernel(
    const float* __restrict__ x,
    const float* __restrict__ W1, const float* __restrict__ b1,
    const float* __restrict__ W2, const float* __restrict__ b2,
    const float* __restrict__ W3, const float* __restrict__ b3,
    const float* __restrict__ W4, const float* __restrict__ b4,
    float* __restrict__ out, float* __restrict__ out_value)
{
    const int bid = blockIdx.x;
    const int tid = threadIdx.x;   // 0..255

    if (bid < NB) {
        // ============================ MLP role =============================
        __shared__ float        s_h[NBINS];
        __shared__ unsigned int s_red[8];
        __shared__ float        s_l1p[8][32];
        __shared__ float        s_h1[32];
        __shared__ float        s_h2[64];
        __shared__ float        s_h3[128];
        __shared__ float        s_p[4];
        __shared__ unsigned int s_key;

        const int b    = bid;
        const int lane = tid & 31;
        const int warp = tid >> 5;

        // Sum 8 chunk partials -> histogram (bin = tid)
        unsigned int cnt;
        {
            unsigned int s = 0;
            const unsigned int* p = &g_hist_partial[(size_t)b * CHUNKS * NBINS + tid];
            #pragma unroll
            for (int c = 0; c < CHUNKS; c++) s += p[c * NBINS];
            cnt = s;
            s_h[tid] = (float)s;
        }

        // First-occurrence argmax via packed key (count<<8)|(255-bin):
        // counts <= 262144 < 2^19 -> fits 27 bits; ties -> LOWEST index.
        unsigned int key = (cnt << 8) | (unsigned)(255 - tid);
        #pragma unroll
        for (int o = 16; o > 0; o >>= 1) {
            unsigned int other = __shfl_down_sync(0xffffffffu, key, o);
            if (other > key) key = other;
        }
        if (lane == 0) s_red[warp] = key;
        __syncthreads();
        if (tid == 0) {
            unsigned int k = s_red[0];
            #pragma unroll
            for (int i = 1; i < 8; i++) if (s_red[i] > k) k = s_red[i];
            s_key = k;
        }
        __syncthreads();

        const int   am = 255 - (int)(s_key & 255u);
        const float ch = (float)(s_key >> 8) * HEIGHT_RT;
        __syncthreads();   // protect s_red reuse

        int mini = (tid >= am && !(s_h[tid] > ch)) ? tid : 0x7fffffff;
        #pragma unroll
        for (int o = 16; o > 0; o >>= 1) {
            int other = __shfl_down_sync(0xffffffffu, mini, o);
            if (other < mini) mini = other;
        }
        if (lane == 0) s_red[warp] = (unsigned)mini;
        __syncthreads();
        if (tid == 0) {
            int m = (int)s_red[0];
            #pragma unroll
            for (int i = 1; i < 8; i++) if ((int)s_red[i] < m) m = (int)s_red[i];
            if (m == 0x7fffffff) m = 0;
            out_value[b] = (float)m / (float)NBINS;
        }

        // Layer 1: 256 -> 32  (8 partials x 32 outputs)
        {
            const int o = tid & 31, pp = tid >> 5;
            float acc = (pp == 0) ? b1[o] : 0.0f;
            const float* w = W1 + o * 256 + pp * 32;
            const float* h = s_h + pp * 32;
            #pragma unroll
            for (int k = 0; k < 32; k++) acc = fmaf(h[k], w[k], acc);
            s_l1p[pp][o] = acc;
        }
        __syncthreads();
        if (tid < 32) {
            float a = 0.0f;
            #pragma unroll
            for (int pp = 0; pp < 8; pp++) a += s_l1p[pp][tid];
            s_h1[tid] = fmaxf(a, 0.0f);
        }
        __syncthreads();

        if (tid < 64) {                           // Layer 2: 32 -> 64
            float acc = b2[tid];
            const float* w = W2 + tid * 32;
            #pragma unroll
            for (int k = 0; k < 32; k++) acc = fmaf(s_h1[k], w[k], acc);
            s_h2[tid] = fmaxf(acc, 0.0f);
        }
        __syncthreads();

        if (tid < 128) {                          // Layer 3: 64 -> 128
            float acc = b3[tid];
            const float* w = W3 + tid * 64;
            #pragma unroll
            for (int k = 0; k < 64; k++) acc = fmaf(s_h2[k], w[k], acc);
            s_h3[tid] = fmaxf(acc, 0.0f);
        }
        __syncthreads();

        float part = (tid < 128) ? s_h3[tid] * W4[tid] : 0.0f;   // Layer 4
        #pragma unroll
        for (int o = 16; o > 0; o >>= 1)
            part += __shfl_down_sync(0xffffffffu, part, o);
        if (lane == 0 && warp < 4) s_p[warp] = part;
        __syncthreads();
        if (tid == 0) {
            g_w[b] = s_p[0] + s_p[1] + s_p[2] + s_p[3] + b4[0];
            __threadfence();                      // publish w before flag
            g_ready[b] = 1u;                      // release
        }
        return;
    }

    // ===================== scale role (R7's exact pass) ====================
    const int tile   = TILES - 1 - (bid - NB);    // reverse sweep
    const int sample = tile >> 6;                 // 64 tiles per sample
    __shared__ float s_w;

    if (tid == 0) {
        while (g_ready[sample] == 0u) __nanosleep(32);
        __threadfence();                          // acquire
        s_w = g_w[sample];
    }
    __syncthreads();
    const float w = s_w;

    const size_t base = (size_t)tile * 1024 + tid;
    const float4* __restrict__ xin = (const float4*)x   + base;
    float4* __restrict__       o   = (float4*)out       + base;
    #pragma unroll
    for (int j = 0; j < 4; j++) {
        float4 v = __ldcs(xin + j * 256);
        v.x *= w; v.y *= w; v.z *= w; v.w *= w;
        __stcs(o + j * 256, v);
    }
}

// ---------------------------------------------------------------------------
extern "C" void kernel_launch(void* const* d_in, const int* in_sizes, int n_in,
                              void* d_out, int out_size)
{
    const float* x  = (const float*)d_in[0];
    const float* W1 = (const float*)d_in[1];
    const float* b1 = (const float*)d_in[2];
    const float* W2 = (const float*)d_in[3];
    const float* b2 = (const float*)d_in[4];
    const float* W3 = (const float*)d_in[5];
    const float* b3 = (const float*)d_in[6];
    const float* W4 = (const float*)d_in[7];
    const float* b4 = (const float*)d_in[8];

    float* out       = (float*)d_out;
    float* out_value = out + OUT_X;

    dim3 hgrid(CHUNKS, NB);
    hist_kernel<<<hgrid, 256>>>(x);
    scale_mlp_kernel<<<NB + TILES, 256>>>(x, W1, b1, W2, b2, W3, b3, W4, b4,
                                          out, out_value);
    (void)in_sizes; (void)n_in; (void)out_size;
}

// round 15
// speedup vs baseline: 1.2513x; 1.0629x over previous
#include <cuda_runtime.h>

// Problem constants (fixed shapes per reference: B=128, C=1, H=W=512, BINS=256)
#define NBINS      256
#define HEIGHT_RT  0.05f
#define NB         128                 // batch
#define NPER       262144              // 512*512 elems per sample
#define CHUNKS     8                   // hist blocks per sample
#define CHUNK_EL   (NPER / CHUNKS)     // 32768 elems per hist block
#define OUT_X      ((size_t)NB * NPER) // big output, then NB values
#define TILES      8192                // scale tiles of 1024 float4

// Scratch (no allocations). Every slot fully overwritten each call.
__device__ unsigned int g_hist_partial[NB * CHUNKS * NBINS];   // 1 MB
__device__ float        g_w[NB];

// ---------------------------------------------------------------------------
// Kernel 1: per-(sample,chunk) histogram. grid = (CHUNKS, NB), 256 threads.
// Warp-private smem copies + atomics. Measured (R7): 25.8 us, DRAM 68%,
// 5.4 TB/s effective (partial L2 hits from previous replay's scale pass).
// ---------------------------------------------------------------------------
__global__ __launch_bounds__(256) void hist_kernel(const float* __restrict__ x) {
    __shared__ unsigned int sh[8][NBINS];
    const int tid    = threadIdx.x;          // 0..255
    const int warp   = tid >> 5;
    const int sample = blockIdx.y;
    const int chunk  = blockIdx.x;

    #pragma unroll
    for (int c = 0; c < 8; c++) sh[c][tid] = 0u;
    __syncthreads();

    const float4* __restrict__ p =
        (const float4*)(x + (size_t)sample * NPER + (size_t)chunk * CHUNK_EL);
    // 8192 float4 per block; 32 per thread
    #pragma unroll 8
    for (int j = 0; j < 32; j++) {
        float4 v = p[j * 256 + tid];
        float vals[4] = {v.x, v.y, v.z, v.w};
        #pragma unroll
        for (int k = 0; k < 4; k++) {
            float f = vals[k];
            if (f >= 0.0f && f <= 1.0f) {        // torch.histc: out-of-range ignored
                int b = (int)(f * 256.0f);       // floor (f >= 0)
                if (b > 255) b = 255;            // f == 1.0 -> last bin
                atomicAdd(&sh[warp][b], 1u);
            }
        }
    }
    __syncthreads();

    unsigned int s = 0;
    #pragma unroll
    for (int c = 0; c < 8; c++) s += sh[c][tid];
    g_hist_partial[((size_t)sample * CHUNKS + chunk) * NBINS + tid] = s;
}

// ---------------------------------------------------------------------------
// Kernel 2: per-sample threshold value + MLP. grid = NB, 256 threads.
// Fully parallel (no serial scans). Measured: ~3 us.
// ---------------------------------------------------------------------------
__global__ __launch_bounds__(256) void mlp_kernel(
    const float* __restrict__ W1, const float* __restrict__ b1,
    const float* __restrict__ W2, const float* __restrict__ b2,
    const float* __restrict__ W3, const float* __restrict__ b3,
    const float* __restrict__ W4, const float* __restrict__ b4,
    float* __restrict__ out_value)
{
    __shared__ float        s_h[NBINS];
    __shared__ unsigned int s_red[8];
    __shared__ float        s_l1p[8][32];
    __shared__ float        s_h1[32];
    __shared__ float        s_h2[64];
    __shared__ float        s_h3[128];
    __shared__ float        s_p[4];
    __shared__ unsigned int s_key;

    const int b    = blockIdx.x;
    const int tid  = threadIdx.x;   // 0..255
    const int lane = tid & 31;
    const int warp = tid >> 5;      // 0..7

    // Sum 8 chunk partials -> histogram (bin = tid)
    unsigned int cnt;
    {
        unsigned int s = 0;
        const unsigned int* p = &g_hist_partial[(size_t)b * CHUNKS * NBINS + tid];
        #pragma unroll
        for (int c = 0; c < CHUNKS; c++) s += p[c * NBINS];
        cnt = s;
        s_h[tid] = (float)s;
    }

    // First-occurrence argmax via packed key (count<<8)|(255-bin):
    // counts <= 262144 < 2^19 -> fits 27 bits; ties go to LOWEST index.
    unsigned int key = (cnt << 8) | (unsigned)(255 - tid);
    #pragma unroll
    for (int o = 16; o > 0; o >>= 1) {
        unsigned int other = __shfl_down_sync(0xffffffffu, key, o);
        if (other > key) key = other;
    }
    if (lane == 0) s_red[warp] = key;
    __syncthreads();
    if (tid == 0) {
        unsigned int k = s_red[0];
        #pragma unroll
        for (int i = 1; i < 8; i++) if (s_red[i] > k) k = s_red[i];
        s_key = k;
    }
    __syncthreads();

    const int   am = 255 - (int)(s_key & 255u);
    const float ch = (float)(s_key >> 8) * HEIGHT_RT;
    __syncthreads();   // protect s_red reuse

    // First i >= am with h[i] <= ch; default 0 if none.
    int mini = (tid >= am && !(s_h[tid] > ch)) ? tid : 0x7fffffff;
    #pragma unroll
    for (int o = 16; o > 0; o >>= 1) {
        int other = __shfl_down_sync(0xffffffffu, mini, o);
        if (other < mini) mini = other;
    }
    if (lane == 0) s_red[warp] = (unsigned)mini;
    __syncthreads();
    if (tid == 0) {
        int m = (int)s_red[0];
        #pragma unroll
        for (int i = 1; i < 8; i++) if ((int)s_red[i] < m) m = (int)s_red[i];
        if (m == 0x7fffffff) m = 0;
        out_value[b] = (float)m / (float)NBINS;
    }

    // Layer 1: 256 -> 32  (8 partials x 32 outputs)
    {
        const int o = tid & 31, pp = tid >> 5;
        float acc = (pp == 0) ? b1[o] : 0.0f;
        const float* w = W1 + o * 256 + pp * 32;
        const float* h = s_h + pp * 32;
        #pragma unroll
        for (int k = 0; k < 32; k++) acc = fmaf(h[k], w[k], acc);
        s_l1p[pp][o] = acc;
    }
    __syncthreads();
    if (tid < 32) {
        float a = 0.0f;
        #pragma unroll
        for (int pp = 0; pp < 8; pp++) a += s_l1p[pp][tid];
        s_h1[tid] = fmaxf(a, 0.0f);
    }
    __syncthreads();

    // Layer 2: 32 -> 64
    if (tid < 64) {
        float acc = b2[tid];
        const float* w = W2 + tid * 32;
        #pragma unroll
        for (int k = 0; k < 32; k++) acc = fmaf(s_h1[k], w[k], acc);
        s_h2[tid] = fmaxf(acc, 0.0f);
    }
    __syncthreads();

    // Layer 3: 64 -> 128
    if (tid < 128) {
        float acc = b3[tid];
        const float* w = W3 + tid * 64;
        #pragma unroll
        for (int k = 0; k < 64; k++) acc = fmaf(s_h2[k], w[k], acc);
        s_h3[tid] = fmaxf(acc, 0.0f);
    }
    __syncthreads();

    // Layer 4: 128 -> 1 (first 4 warps)
    float part = (tid < 128) ? s_h3[tid] * W4[tid] : 0.0f;
    #pragma unroll
    for (int o = 16; o > 0; o >>= 1)
        part += __shfl_down_sync(0xffffffffu, part, o);
    if (lane == 0 && warp < 4) s_p[warp] = part;
    __syncthreads();
    if (tid == 0)
        g_w[b] = s_p[0] + s_p[1] + s_p[2] + s_p[3] + b4[0];
}

// ---------------------------------------------------------------------------
// Kernel 3: out = x * w[sample], REVERSE tile order (R7). grid = TILES.
// DELTA vs R7: all 4 loads issued BEFORE any store (front-batched LDG,
// MLP_p1 1 -> 4) so the independent reads overlap the write drain instead
// of serializing behind it. __ldcs on last-use x; __stcs streaming writes.
// ---------------------------------------------------------------------------
__global__ __launch_bounds__(256) void scale_kernel(const float* __restrict__ x,
                                                    float* __restrict__ out)
{
    const int tile   = TILES - 1 - blockIdx.x;    // reverse sweep
    const int sample = tile >> 6;                 // 64 tiles per sample
    const float w    = g_w[sample];

    const size_t base = (size_t)tile * 1024 + threadIdx.x;
    const float4* __restrict__ xin = (const float4*)x   + base;
    float4* __restrict__       o   = (float4*)out       + base;

    float4 v0 = __ldcs(xin + 0 * 256);
    float4 v1 = __ldcs(xin + 1 * 256);
    float4 v2 = __ldcs(xin + 2 * 256);
    float4 v3 = __ldcs(xin + 3 * 256);

    v0.x *= w; v0.y *= w; v0.z *= w; v0.w *= w;
    v1.x *= w; v1.y *= w; v1.z *= w; v1.w *= w;
    v2.x *= w; v2.y *= w; v2.z *= w; v2.w *= w;
    v3.x *= w; v3.y *= w; v3.z *= w; v3.w *= w;

    __stcs(o + 0 * 256, v0);
    __stcs(o + 1 * 256, v1);
    __stcs(o + 2 * 256, v2);
    __stcs(o + 3 * 256, v3);
}

// ---------------------------------------------------------------------------
extern "C" void kernel_launch(void* const* d_in, const int* in_sizes, int n_in,
                              void* d_out, int out_size)
{
    const float* x  = (const float*)d_in[0];
    const float* W1 = (const float*)d_in[1];
    const float* b1 = (const float*)d_in[2];
    const float* W2 = (const float*)d_in[3];
    const float* b2 = (const float*)d_in[4];
    const float* W3 = (const float*)d_in[5];
    const float* b3 = (const float*)d_in[6];
    const float* W4 = (const float*)d_in[7];
    const float* b4 = (const float*)d_in[8];

    float* out       = (float*)d_out;
    float* out_value = out + OUT_X;

    dim3 hgrid(CHUNKS, NB);
    hist_kernel<<<hgrid, 256>>>(x);
    mlp_kernel<<<NB, 256>>>(W1, b1, W2, b2, W3, b3, W4, b4, out_value);
    scale_kernel<<<TILES, 256>>>(x, out);
    (void)in_sizes; (void)n_in; (void)out_size;
}